// round 1
// baseline (speedup 1.0000x reference)
#include <cuda_runtime.h>

// NTM memory read, fused single-pass over the 128MB `memory` tensor.
//
// read[b,m] = (Σ_n e_n·z_n·memory[b,n,m]) / (Σ_n e_n)
//           + ((Σ_n e_n·w_w_n) / (Σ_n e_n)) · k[b,m]
// where e_n = exp(cos(memory[b,n,:], k[b,:])), z_n = 1 - w_lu_prev[b,n],
//       w_w_n = g·w_r_prev[b,n] + (1-g)·w_lu_prev[b,n].
// Cosine ∈ [-1,1] so exp() never over/underflows -> no max-subtraction needed;
// normalization happens once in the merge kernel. The w_u / nth-smallest /
// w_lu / gamma branch of the reference is dead code for `read` and is skipped.

#define NB   64            // batch
#define NN   2048          // rows
#define NM   256           // columns
#define WPB  64            // warps per batch
#define RPW  (NN / WPB)    // 32 rows per warp
#define TPB  256           // threads per block
#define WPBL 8             // warps per block
#define BLPB (WPB / WPBL)  // 8 blocks per batch

// Scratch: per-(batch,warp) partials. 64*64*256*4 = 4 MB + scalars.
__device__ float g_acc[NB][WPB][NM];
__device__ float g_se[NB][WPB];
__device__ float g_sw[NB][WPB];

__global__ void __launch_bounds__(TPB)
ntm_pass1(const float* __restrict__ mem,
          const float* __restrict__ kk,
          const float* __restrict__ gg,
          const float* __restrict__ w_prev,
          const int*   __restrict__ w_lu)
{
    const int b    = blockIdx.y;
    const int wIn  = blockIdx.x * WPBL + (threadIdx.x >> 5);  // warp index within batch
    const int lane = threadIdx.x & 31;
    const int n0   = wIn * RPW;

    // Lane l owns columns {4l..4l+3} and {128+4l..128+4l+3}.
    const float4* k4 = reinterpret_cast<const float4*>(kk + (size_t)b * NM);
    const float4 ka = k4[lane];
    const float4 kb = k4[32 + lane];

    // ||k|| (warp reduce of per-lane sumsq)
    float ksq = ka.x*ka.x + ka.y*ka.y + ka.z*ka.z + ka.w*ka.w
              + kb.x*kb.x + kb.y*kb.y + kb.z*kb.z + kb.w*kb.w;
    #pragma unroll
    for (int off = 16; off; off >>= 1)
        ksq += __shfl_xor_sync(0xffffffffu, ksq, off);
    const float inv_knrm = 1.0f / fmaxf(sqrtf(ksq), 1e-8f);

    // Per-row scalars: preload one row per lane (RPW == 32), broadcast via shfl.
    const float gb    = gg[b];
    const float wluf  = (float)w_lu[(size_t)b * NN + n0 + lane];
    const float zf_l  = 1.0f - wluf;
    const float ww_l  = gb * w_prev[(size_t)b * 2 * NN + NN + n0 + lane]
                      + (1.0f - gb) * wluf;

    float a0=0.f,a1=0.f,a2=0.f,a3=0.f,a4=0.f,a5=0.f,a6=0.f,a7=0.f;
    float se = 0.f, sw = 0.f;

    const float4* rb = reinterpret_cast<const float4*>(
        mem + ((size_t)b * NN + n0) * NM);

    #pragma unroll 4
    for (int r = 0; r < RPW; r++) {
        const float4 va = rb[(size_t)r * 64 + lane];
        const float4 vb = rb[(size_t)r * 64 + 32 + lane];

        float dot = va.x*ka.x + va.y*ka.y + va.z*ka.z + va.w*ka.w
                  + vb.x*kb.x + vb.y*kb.y + vb.z*kb.z + vb.w*kb.w;
        float sq  = va.x*va.x + va.y*va.y + va.z*va.z + va.w*va.w
                  + vb.x*vb.x + vb.y*vb.y + vb.z*vb.z + vb.w*vb.w;

        #pragma unroll
        for (int off = 16; off; off >>= 1) {
            dot += __shfl_xor_sync(0xffffffffu, dot, off);
            sq  += __shfl_xor_sync(0xffffffffu, sq,  off);
        }

        const float score = dot * inv_knrm / fmaxf(sqrtf(sq), 1e-8f);
        const float e  = __expf(score);
        const float zf = __shfl_sync(0xffffffffu, zf_l, r);
        const float ww = __shfl_sync(0xffffffffu, ww_l, r);

        se += e;
        sw += e * ww;
        const float ez = e * zf;
        a0 += ez * va.x;  a1 += ez * va.y;  a2 += ez * va.z;  a3 += ez * va.w;
        a4 += ez * vb.x;  a5 += ez * vb.y;  a6 += ez * vb.z;  a7 += ez * vb.w;
    }

    float4* ao = reinterpret_cast<float4*>(&g_acc[b][wIn][0]);
    ao[lane]      = make_float4(a0, a1, a2, a3);
    ao[32 + lane] = make_float4(a4, a5, a6, a7);
    if (lane == 0) {
        g_se[b][wIn] = se;
        g_sw[b][wIn] = sw;
    }
}

__global__ void __launch_bounds__(NM)
ntm_pass2(const float* __restrict__ kk, float* __restrict__ out)
{
    const int b = blockIdx.x;
    const int m = threadIdx.x;

    __shared__ float s_inv_denom, s_sfac;
    if (m < 32) {
        float se = g_se[b][m] + g_se[b][m + 32];
        float sw = g_sw[b][m] + g_sw[b][m + 32];
        #pragma unroll
        for (int off = 16; off; off >>= 1) {
            se += __shfl_xor_sync(0xffffffffu, se, off);
            sw += __shfl_xor_sync(0xffffffffu, sw, off);
        }
        if (m == 0) {
            s_inv_denom = 1.0f / se;
            s_sfac      = sw / se;
        }
    }
    __syncthreads();

    float a = 0.0f;
    #pragma unroll
    for (int w = 0; w < WPB; w++)
        a += g_acc[b][w][m];

    out[(size_t)b * NM + m] = a * s_inv_denom + s_sfac * kk[(size_t)b * NM + m];
}

extern "C" void kernel_launch(void* const* d_in, const int* in_sizes, int n_in,
                              void* d_out, int out_size)
{
    const float* mem    = (const float*)d_in[0];  // [B,N,M] f32
    const float* k      = (const float*)d_in[1];  // [B,M]   f32
    const float* g      = (const float*)d_in[2];  // [B,1]   f32
    // d_in[3] = gamma (dead for output), d_in[6] = n (dead for output)
    const float* w_prev = (const float*)d_in[4];  // [B,2,N] f32
    const int*   w_lu   = (const int*)  d_in[5];  // [B,N]   i32
    float*       out    = (float*)d_out;          // [B,M]   f32

    dim3 grid1(BLPB, NB);
    ntm_pass1<<<grid1, TPB>>>(mem, k, g, w_prev, w_lu);
    ntm_pass2<<<NB, NM>>>(k, out);
}

// round 3
// speedup vs baseline: 1.0482x; 1.0482x over previous
#include <cuda_runtime.h>

// NTM memory read, fused single-pass over the 128MB `memory` tensor,
// with in-kernel (last-block-per-batch) final reduction.
//
// read[b,m] = (Σ_n e_n·z_n·memory[b,n,m]) / (Σ_n e_n)
//           + ((Σ_n e_n·w_w_n) / (Σ_n e_n)) · k[b,m]
// e_n = exp(cos(memory[b,n,:], k[b,:])), z_n = 1 - w_lu_prev[b,n],
// w_w_n = g·w_r_prev[b,n] + (1-g)·w_lu_prev[b,n].
// Cosine ∈ [-1,1] so exp() is safe without max-subtraction; normalization is
// applied once at the end. The w_u / nth-smallest / w_lu / gamma branch of the
// reference is dead code for `read` and is skipped.
//
// Shuffle economy per row (vs 12 in the naive version):
//   2  xor-16 on dot & sq
//   4  combined butterfly (lo-half reduces dot, hi-half reduces sq)
//   1  xor-16 exchange so every lane holds both sums
//   0  zf: precomputed ballot mask;  0  ww: lane-local e capture

#define NB    64            // batch
#define NN    2048          // rows
#define NM    256           // columns
#define TPB   256           // threads per block
#define NWARP 8             // warps per block
#define BLPB  8             // blocks per batch
#define WPB   (BLPB*NWARP)  // 64 warps per batch
#define RPW   (NN / WPB)    // 32 rows per warp
#define FULL  0xffffffffu

// Per-(batch,block) partials: 64*8*256*4 = 512 KB (+ scalars, counter).
__device__ float g_acc[NB][BLPB][NM];
__device__ float g_se[NB][BLPB];
__device__ float g_sw[NB][BLPB];
__device__ int   g_cnt[NB];   // zero-initialized; reset by finalizing block

__device__ __forceinline__ float bfly_sum(float v) {
    #pragma unroll
    for (int off = 16; off; off >>= 1)
        v += __shfl_xor_sync(FULL, v, off);
    return v;
}

__global__ void __launch_bounds__(TPB)
ntm_fused(const float* __restrict__ mem,
          const float* __restrict__ kk,
          const float* __restrict__ gg,
          const float* __restrict__ w_prev,
          const int*   __restrict__ w_lu,
          float*       __restrict__ out)
{
    const int b    = blockIdx.y;
    const int blk  = blockIdx.x;                  // block index within batch
    const int warp = threadIdx.x >> 5;
    const int lane = threadIdx.x & 31;
    const int wIn  = blk * NWARP + warp;          // warp index within batch
    const int n0   = wIn * RPW;
    const bool lo  = lane < 16;

    // Lane l owns columns {4l..4l+3} and {128+4l..128+4l+3}.
    const float4* k4 = reinterpret_cast<const float4*>(kk + (size_t)b * NM);
    const float4 ka = k4[lane];
    const float4 kb = k4[32 + lane];

    float ksq = ka.x*ka.x + ka.y*ka.y + ka.z*ka.z + ka.w*ka.w
              + kb.x*kb.x + kb.y*kb.y + kb.z*kb.z + kb.w*kb.w;
    const float inv_knrm = 1.0f / fmaxf(sqrtf(bfly_sum(ksq)), 1e-8f);

    // Per-row scalars: one row per lane (RPW == 32).
    const float gb   = gg[b];
    const float wluf = (float)w_lu[(size_t)b * NN + n0 + lane];
    const float ww_l = gb * w_prev[(size_t)b * 2 * NN + NN + n0 + lane]
                     + (1.0f - gb) * wluf;
    // Bit r of zmask == (w_lu_prev[row n0+r] == 0), i.e. z_r.
    const unsigned zmask = __ballot_sync(FULL, wluf == 0.0f);

    float a0=0.f,a1=0.f,a2=0.f,a3=0.f,a4=0.f,a5=0.f,a6=0.f,a7=0.f;
    float e_mine = 0.f;   // e for row (n0 + lane), captured when r == lane

    const float4* rb = reinterpret_cast<const float4*>(
        mem + ((size_t)b * NN + n0) * NM);

    #pragma unroll 4
    for (int r = 0; r < RPW; r++) {
        const float4 va = rb[(size_t)r * 64 + lane];
        const float4 vb = rb[(size_t)r * 64 + 32 + lane];

        float dot = va.x*ka.x + va.y*ka.y + va.z*ka.z + va.w*ka.w
                  + vb.x*kb.x + vb.y*kb.y + vb.z*kb.z + vb.w*kb.w;
        float sq  = va.x*va.x + va.y*va.y + va.z*va.z + va.w*va.w
                  + vb.x*vb.x + vb.y*vb.y + vb.z*vb.z + vb.w*vb.w;

        // Paired-halves warp reduction: 7 shuffles for two full sums.
        dot += __shfl_xor_sync(FULL, dot, 16);
        sq  += __shfl_xor_sync(FULL, sq,  16);
        float c = lo ? dot : sq;
        c += __shfl_xor_sync(FULL, c, 8);
        c += __shfl_xor_sync(FULL, c, 4);
        c += __shfl_xor_sync(FULL, c, 2);
        c += __shfl_xor_sync(FULL, c, 1);
        const float p    = __shfl_xor_sync(FULL, c, 16);
        const float dotf = lo ? c : p;
        const float sqf  = lo ? p : c;

        const float score = dotf * inv_knrm / fmaxf(sqrtf(sqf), 1e-8f);
        const float e  = __expf(score);
        if (r == lane) e_mine = e;                  // predicated select
        const float ez = ((zmask >> r) & 1u) ? e : 0.0f;

        a0 += ez * va.x;  a1 += ez * va.y;  a2 += ez * va.z;  a3 += ez * va.w;
        a4 += ez * vb.x;  a5 += ez * vb.y;  a6 += ez * vb.z;  a7 += ez * vb.w;
    }

    // Once-per-warp scalar reductions (deferred from the hot loop).
    float se = bfly_sum(e_mine);
    float sw = bfly_sum(e_mine * ww_l);

    // ---- Block-level reduction of the 8 warps' partials through smem ----
    __shared__ float s_acc[NWARP][NM];   // 8 KB
    __shared__ float s_se[NWARP], s_sw[NWARP];
    __shared__ int   s_last;
    __shared__ float s_invden, s_sfac;

    float4* sa = reinterpret_cast<float4*>(&s_acc[warp][0]);
    sa[lane]      = make_float4(a0, a1, a2, a3);
    sa[32 + lane] = make_float4(a4, a5, a6, a7);
    if (lane == 0) { s_se[warp] = se; s_sw[warp] = sw; }
    __syncthreads();

    const int t = threadIdx.x;
    float bsum = 0.f;
    #pragma unroll
    for (int w = 0; w < NWARP; w++) bsum += s_acc[w][t];
    g_acc[b][blk][t] = bsum;
    if (t == 0) {
        float bse = 0.f, bsw = 0.f;
        #pragma unroll
        for (int w = 0; w < NWARP; w++) { bse += s_se[w]; bsw += s_sw[w]; }
        g_se[b][blk] = bse;
        g_sw[b][blk] = bsw;
    }

    // ---- Last block of this batch finalizes (deterministic fixed-order sums) ----
    __threadfence();
    if (t == 0) {
        int old = atomicAdd(&g_cnt[b], 1);
        s_last = (old == BLPB - 1);
    }
    __syncthreads();
    if (!s_last) return;

    float fa = 0.f;
    #pragma unroll
    for (int w = 0; w < BLPB; w++) fa += g_acc[b][w][t];

    if (t == 0) {
        float fse = 0.f, fsw = 0.f;
        #pragma unroll
        for (int w = 0; w < BLPB; w++) { fse += g_se[b][w]; fsw += g_sw[b][w]; }
        s_invden = 1.0f / fse;
        s_sfac   = fsw / fse;
        g_cnt[b] = 0;                     // reset for next graph replay
    }
    __syncthreads();

    out[(size_t)b * NM + t] = fa * s_invden + s_sfac * kk[(size_t)b * NM + t];
}

extern "C" void kernel_launch(void* const* d_in, const int* in_sizes, int n_in,
                              void* d_out, int out_size)
{
    const float* mem    = (const float*)d_in[0];  // [B,N,M] f32
    const float* k      = (const float*)d_in[1];  // [B,M]   f32
    const float* g      = (const float*)d_in[2];  // [B,1]   f32
    // d_in[3] = gamma, d_in[6] = n : dead for the output
    const float* w_prev = (const float*)d_in[4];  // [B,2,N] f32
    const int*   w_lu   = (const int*)  d_in[5];  // [B,N]   i32
    float*       out    = (float*)d_out;          // [B,M]   f32

    dim3 grid(BLPB, NB);
    ntm_fused<<<grid, TPB>>>(mem, k, g, w_prev, w_lu, out);
}

// round 4
// speedup vs baseline: 1.2000x; 1.1448x over previous
#include <cuda_runtime.h>

// NTM memory read, fused single-pass over the 128MB `memory` tensor.
// Half-warp row decomposition: each 16-lane half processes one row per
// iteration (2 rows/warp/iter), cutting cross-lane reduction to 3 shfls/row
// and halving the per-row serial chain. In-kernel last-block finalization.
//
// read[b,m] = (Σ_n e_n·z_n·memory[b,n,m]) / (Σ_n e_n)
//           + ((Σ_n e_n·w_w_n) / (Σ_n e_n)) · k[b,m]
// e_n = exp(cos(mem[b,n,:], k[b,:])), z_n = 1-w_lu_prev, w_w = g·w_r_prev+(1-g)·w_lu_prev.
// cos ∈ [-1,1] -> exp safe without max-subtraction. w_u/sort/gamma branch is
// dead code for `read`. rsqrt(max(sq,1e-16)) == 1/max(norm,1e-8) exactly.

#define NB    64            // batch
#define NN    2048          // rows
#define NM    256           // columns
#define TPB   128           // threads per block
#define NWARP 4             // warps per block
#define BLPB  16            // blocks per batch  -> grid 1024 (one full wave @7/SM)
#define WPB   (BLPB*NWARP)  // 64 warps per batch
#define RPW   (NN / WPB)    // 32 rows per warp  (16 iterations x 2 rows)
#define NITER (RPW/2)
#define FULL  0xffffffffu

__device__ float g_acc[NB][BLPB][NM];   // 1 MB partials
__device__ float g_se[NB][BLPB];
__device__ float g_sw[NB][BLPB];
__device__ int   g_cnt[NB];             // zero-init; reset by finalizing block

__device__ __forceinline__ float bfly16(float v) {  // sum within 16-lane half
    #pragma unroll
    for (int off = 8; off; off >>= 1) v += __shfl_xor_sync(FULL, v, off);
    return v;
}
__device__ __forceinline__ float bfly32(float v) {
    #pragma unroll
    for (int off = 16; off; off >>= 1) v += __shfl_xor_sync(FULL, v, off);
    return v;
}

__global__ void __launch_bounds__(TPB, 7)
ntm_fused(const float* __restrict__ mem,
          const float* __restrict__ kk,
          const float* __restrict__ gg,
          const float* __restrict__ w_prev,
          const int*   __restrict__ w_lu,
          float*       __restrict__ out)
{
    const int b    = blockIdx.y;
    const int blk  = blockIdx.x;
    const int warp = threadIdx.x >> 5;
    const int lane = threadIdx.x & 31;
    const int h    = lane >> 4;          // half: 0 = even row, 1 = odd row
    const int hl   = lane & 15;          // lane within half
    const int wIn  = blk * NWARP + warp;
    const int n0   = wIn * RPW;

    // Each lane owns 16 k-columns: float4 slots {hl, 16+hl, 32+hl, 48+hl}.
    const float4* k4 = reinterpret_cast<const float4*>(kk + (size_t)b * NM);
    const float4 ka0 = k4[hl],      ka1 = k4[16 + hl];
    const float4 ka2 = k4[32 + hl], ka3 = k4[48 + hl];

    float ksq = ka0.x*ka0.x + ka0.y*ka0.y + ka0.z*ka0.z + ka0.w*ka0.w
              + ka1.x*ka1.x + ka1.y*ka1.y + ka1.z*ka1.z + ka1.w*ka1.w
              + ka2.x*ka2.x + ka2.y*ka2.y + ka2.z*ka2.z + ka2.w*ka2.w
              + ka3.x*ka3.x + ka3.y*ka3.y + ka3.z*ka3.z + ka3.w*ka3.w;
    const float inv_knrm = __frsqrt_rn(fmaxf(bfly16(ksq), 1e-16f));

    // Row metadata, remapped so ballot bits / e-capture line up per half:
    // lane's designated row = 2*hl + h;  iter r: lo half does row 2r, hi 2r+1.
    const int   myrow = (hl << 1) | h;
    const float gb    = gg[b];
    const float wluf  = (float)w_lu[(size_t)b * NN + n0 + myrow];
    const float ww_l  = gb * w_prev[(size_t)b * 2 * NN + NN + n0 + myrow]
                      + (1.0f - gb) * wluf;
    const unsigned zmask = __ballot_sync(FULL, wluf == 0.0f);
    const int      zsh   = h << 4;       // lo tests bit r, hi tests bit 16+r

    float acc[16];
    #pragma unroll
    for (int i = 0; i < 16; i++) acc[i] = 0.0f;
    float e_mine = 0.0f;

    const float4* rb = reinterpret_cast<const float4*>(
        mem + ((size_t)b * NN + n0) * NM);

    #pragma unroll 2
    for (int r = 0; r < NITER; r++) {
        const float4* rp = rb + (size_t)(2 * r + h) * 64;
        const float4 v0 = rp[hl];
        const float4 v1 = rp[16 + hl];
        const float4 v2 = rp[32 + hl];
        const float4 v3 = rp[48 + hl];

        float d0 = v0.x*ka0.x + v0.y*ka0.y + v0.z*ka0.z + v0.w*ka0.w;
        float d1 = v1.x*ka1.x + v1.y*ka1.y + v1.z*ka1.z + v1.w*ka1.w;
        float d2 = v2.x*ka2.x + v2.y*ka2.y + v2.z*ka2.z + v2.w*ka2.w;
        float d3 = v3.x*ka3.x + v3.y*ka3.y + v3.z*ka3.z + v3.w*ka3.w;
        float s0 = v0.x*v0.x + v0.y*v0.y + v0.z*v0.z + v0.w*v0.w;
        float s1 = v1.x*v1.x + v1.y*v1.y + v1.z*v1.z + v1.w*v1.w;
        float s2 = v2.x*v2.x + v2.y*v2.y + v2.z*v2.z + v2.w*v2.w;
        float s3 = v3.x*v3.x + v3.y*v3.y + v3.z*v3.z + v3.w*v3.w;
        float dot = (d0 + d1) + (d2 + d3);
        float sq  = (s0 + s1) + (s2 + s3);

        // 6 shfls -> both full-half sums on every lane (3 shfls/row).
        dot += __shfl_xor_sync(FULL, dot, 8);
        sq  += __shfl_xor_sync(FULL, sq,  8);
        float c = (lane & 8) ? sq : dot;
        c += __shfl_xor_sync(FULL, c, 4);
        c += __shfl_xor_sync(FULL, c, 2);
        c += __shfl_xor_sync(FULL, c, 1);
        const float p  = __shfl_xor_sync(FULL, c, 8);
        const float df = (lane & 8) ? p : c;
        const float sf = (lane & 8) ? c : p;

        const float score = df * inv_knrm * __frsqrt_rn(fmaxf(sf, 1e-16f));
        const float e = __expf(score);
        if (r == hl) e_mine = e;                          // my designated row
        const float ez = ((zmask >> (r + zsh)) & 1u) ? e : 0.0f;

        acc[0]  += ez * v0.x;  acc[1]  += ez * v0.y;  acc[2]  += ez * v0.z;  acc[3]  += ez * v0.w;
        acc[4]  += ez * v1.x;  acc[5]  += ez * v1.y;  acc[6]  += ez * v1.z;  acc[7]  += ez * v1.w;
        acc[8]  += ez * v2.x;  acc[9]  += ez * v2.y;  acc[10] += ez * v2.z;  acc[11] += ez * v2.w;
        acc[12] += ez * v3.x;  acc[13] += ez * v3.y;  acc[14] += ez * v3.z;  acc[15] += ez * v3.w;
    }

    // Warp scalar sums (e_mine covers all 32 rows bijectively).
    const float se = bfly32(e_mine);
    const float sw = bfly32(e_mine * ww_l);

    // Combine the two halves' column accumulators (same columns, 2 rows each).
    #pragma unroll
    for (int i = 0; i < 16; i++) acc[i] += __shfl_xor_sync(FULL, acc[i], 16);

    // ---- Block-level reduction through smem ----
    __shared__ float s_acc[NWARP][NM];     // 4 KB
    __shared__ float s_se[NWARP], s_sw[NWARP];
    __shared__ int   s_last;
    __shared__ float s_invden, s_sfac;

    if (h == 0) {
        float4* sa = reinterpret_cast<float4*>(&s_acc[warp][0]);
        sa[hl]      = make_float4(acc[0],  acc[1],  acc[2],  acc[3]);
        sa[16 + hl] = make_float4(acc[4],  acc[5],  acc[6],  acc[7]);
        sa[32 + hl] = make_float4(acc[8],  acc[9],  acc[10], acc[11]);
        sa[48 + hl] = make_float4(acc[12], acc[13], acc[14], acc[15]);
    }
    if (lane == 0) { s_se[warp] = se; s_sw[warp] = sw; }
    __syncthreads();

    const int t = threadIdx.x;             // 0..127, handles cols t and t+128
    float b0 = 0.f, b1 = 0.f;
    #pragma unroll
    for (int w = 0; w < NWARP; w++) { b0 += s_acc[w][t]; b1 += s_acc[w][t + 128]; }
    g_acc[b][blk][t]       = b0;
    g_acc[b][blk][t + 128] = b1;
    if (t == 0) {
        float bse = 0.f, bsw = 0.f;
        #pragma unroll
        for (int w = 0; w < NWARP; w++) { bse += s_se[w]; bsw += s_sw[w]; }
        g_se[b][blk] = bse;
        g_sw[b][blk] = bsw;
    }

    // ---- Last block per batch finalizes (deterministic fixed-order sums) ----
    __threadfence();
    if (t == 0) {
        int old = atomicAdd(&g_cnt[b], 1);
        s_last = (old == BLPB - 1);
    }
    __syncthreads();
    if (!s_last) return;

    float f0 = 0.f, f1 = 0.f;
    #pragma unroll
    for (int w = 0; w < BLPB; w++) { f0 += g_acc[b][w][t]; f1 += g_acc[b][w][t + 128]; }

    if (t == 0) {
        float fse = 0.f, fsw = 0.f;
        #pragma unroll
        for (int w = 0; w < BLPB; w++) { fse += g_se[b][w]; fsw += g_sw[b][w]; }
        s_invden = 1.0f / fse;
        s_sfac   = fsw / fse;
        g_cnt[b] = 0;                      // reset for next graph replay
    }
    __syncthreads();

    const float* kb = kk + (size_t)b * NM;
    out[(size_t)b * NM + t]       = f0 * s_invden + s_sfac * kb[t];
    out[(size_t)b * NM + t + 128] = f1 * s_invden + s_sfac * kb[t + 128];
}

extern "C" void kernel_launch(void* const* d_in, const int* in_sizes, int n_in,
                              void* d_out, int out_size)
{
    const float* mem    = (const float*)d_in[0];  // [B,N,M] f32
    const float* k      = (const float*)d_in[1];  // [B,M]   f32
    const float* g      = (const float*)d_in[2];  // [B,1]   f32
    // d_in[3] = gamma, d_in[6] = n : dead for the output
    const float* w_prev = (const float*)d_in[4];  // [B,2,N] f32
    const int*   w_lu   = (const int*)  d_in[5];  // [B,N]   i32
    float*       out    = (float*)d_out;          // [B,M]   f32

    dim3 grid(BLPB, NB);
    ntm_fused<<<grid, TPB>>>(mem, k, g, w_prev, w_lu, out);
}